// round 15
// baseline (speedup 1.0000x reference)
#include <cuda_runtime.h>
#include <cuda_fp16.h>
#include <cstdint>

#define NN 50000
#define EE 800000
#define CH 256

// ---- scratch (device globals; no allocation allowed) ----
__device__ __align__(16) __half g_xwh[(size_t)NN * CH];    // x @ W (25.6 MB, fp16)
__device__ int   g_deg[NN];
__device__ int   g_off[NN + 1];
__device__ int   g_cur[NN];
__device__ __align__(16) int2  g_epack[EE];                // (src, val)
__device__ __align__(16) float g_wtf[CH * CH];             // W^T fp32 [n][k]

// =============================================================== helpers
__device__ __forceinline__ uint32_t smem_u32(const void* p) {
    uint32_t a;
    asm("{ .reg .u64 t; cvta.to.shared.u64 t, %1; cvt.u32.u64 %0, t; }"
        : "=r"(a) : "l"(p));
    return a;
}

__device__ __forceinline__ void cp_async16(uint32_t s, const void* g) {
    asm volatile("cp.async.cg.shared.global [%0], [%1], 16;" :: "r"(s), "l"(g));
}
__device__ __forceinline__ void cp_async16z(uint32_t s, const void* g, unsigned sz) {
    asm volatile("cp.async.cg.shared.global [%0], [%1], 16, %2;"
                 :: "r"(s), "l"(g), "r"(sz));
}
__device__ __forceinline__ void cp_commit() {
    asm volatile("cp.async.commit_group;" ::: "memory");
}
template <int N>
__device__ __forceinline__ void cp_wait() {
    asm volatile("cp.async.wait_group %0;" :: "n"(N) : "memory");
}

__device__ __forceinline__ uint32_t lds32(uint32_t addr) {
    uint32_t u;
    asm volatile("ld.shared.b32 %0, [%1];" : "=r"(u) : "r"(addr));
    return u;
}

__device__ __forceinline__ uint32_t f2tf32(uint32_t bits) {
    float v = __uint_as_float(bits);
    uint32_t t;
    asm("cvt.rna.tf32.f32 %0, %1;" : "=r"(t) : "f"(v));
    return t;
}

// D(fp32) += A(tf32) * B(tf32), m16n8k8
__device__ __forceinline__ void mma_tf32(float* c, const uint32_t* a, const uint32_t* b) {
    asm volatile(
        "mma.sync.aligned.m16n8k8.row.col.f32.tf32.tf32.f32 "
        "{%0,%1,%2,%3}, {%4,%5,%6,%7}, {%8,%9}, {%0,%1,%2,%3};"
        : "+f"(c[0]), "+f"(c[1]), "+f"(c[2]), "+f"(c[3])
        : "r"(a[0]), "r"(a[1]), "r"(a[2]), "r"(a[3]), "r"(b[0]), "r"(b[1]));
}

// =============================================================== CSR build
__global__ void hist_kernel(const int* __restrict__ dst, int E) {
    int i = blockIdx.x * blockDim.x + threadIdx.x;
    if (i < E) atomicAdd(&g_deg[dst[i]], 1);
}

// single-pass SMEM scan: 1024 threads x 49 elements each (50176 >= NN)
#define SCAN_PER_T 49
#define SCAN_PAD   (1024 * SCAN_PER_T)           // 50176
#define SCAN_SMEM  (SCAN_PAD * 4)                // 200704 B

__global__ __launch_bounds__(1024) void scan_smem_kernel(int E) {
    extern __shared__ int sd[];
    __shared__ int wsum[32];
    int tid = threadIdx.x, lane = tid & 31, warp = tid >> 5;

    for (int i = tid; i < SCAN_PAD; i += 1024)
        sd[i] = (i < NN) ? g_deg[i] : 0;
    __syncthreads();

    int base = tid * SCAN_PER_T;
    int local = 0;
    for (int j = 0; j < SCAN_PER_T; j++) local += sd[base + j];

    int x = local;
    #pragma unroll
    for (int o = 1; o < 32; o <<= 1) {
        int y = __shfl_up_sync(0xffffffffu, x, o);
        if (lane >= o) x += y;
    }
    if (lane == 31) wsum[warp] = x;
    __syncthreads();
    if (warp == 0) {
        int t = wsum[lane];
        #pragma unroll
        for (int o = 1; o < 32; o <<= 1) {
            int y = __shfl_up_sync(0xffffffffu, t, o);
            if (lane >= o) t += y;
        }
        wsum[lane] = t;
    }
    __syncthreads();
    int run = x - local + (warp > 0 ? wsum[warp - 1] : 0);

    for (int j = 0; j < SCAN_PER_T; j++) {
        int v = sd[base + j];
        sd[base + j] = run;
        run += v;
    }
    __syncthreads();
    for (int i = tid; i < NN; i += 1024) {
        int v = sd[i];
        g_off[i] = v;
        g_cur[i] = v;
    }
    if (tid == 0) g_off[NN] = E;
}

__global__ void scatter_kernel(const int* __restrict__ src,
                               const int* __restrict__ dst,
                               const float* __restrict__ val, int E) {
    int i = blockIdx.x * blockDim.x + threadIdx.x;
    if (i < E) {
        int p = atomicAdd(&g_cur[dst[i]], 1);
        g_epack[p] = make_int2(src[i], __float_as_int(val[i]));
    }
}

// =============================================================== W transpose
__global__ void wt_kernel(const float* __restrict__ W) {
    __shared__ float t[32][33];
    int bx = blockIdx.x * 32, by = blockIdx.y * 32;
    int tx = threadIdx.x, ty = threadIdx.y;
    #pragma unroll
    for (int r = 0; r < 32; r += 8)
        t[ty + r][tx] = W[(size_t)(bx + ty + r) * CH + by + tx];
    __syncthreads();
    #pragma unroll
    for (int r = 0; r < 32; r += 8)
        g_wtf[(size_t)(by + ty + r) * CH + bx + tx] = t[tx][ty + r];
}

// =============================================================== tf32 GEMM
// (R14 version, unchanged — measured good)
#define GEMM_SMEM 65536

__global__ __launch_bounds__(256, 2) void gemm_mma(const float* __restrict__ x,
                                                   int M, int bn) {
    extern __shared__ char smem[];
    const uint32_t sb = smem_u32(smem);
    const int tid  = threadIdx.x;
    const int lane = tid & 31;
    const int wid  = tid >> 5;
    const int warp_m = (wid & 3) * 32;
    const int warp_n = (wid >> 2) * 64;
    const size_t arow = (size_t)blockIdx.x * 128;
    const int g  = lane >> 2;
    const int t4 = lane & 3;

    float acc[2][8][4];
    #pragma unroll
    for (int mt = 0; mt < 2; mt++)
        #pragma unroll
        for (int nt = 0; nt < 8; nt++)
            #pragma unroll
            for (int j = 0; j < 4; j++) acc[mt][nt][j] = 0.f;

    auto taddr = [](uint32_t base, int r, int k) {
        return base + (uint32_t)(r * 128 + (((k >> 2) ^ (r & 7)) * 16) + (k & 3) * 4);
    };

    auto fill = [&](int buf, int ch) {
        const int k0 = ch * 32;
        const uint32_t base = sb + buf * 32768;
        #pragma unroll
        for (int i = 0; i < 4; i++) {
            int chunk = tid + i * 256;
            int r = chunk >> 3, c = chunk & 7;
            uint32_t so = (uint32_t)(r * 128 + ((c ^ (r & 7)) * 16));
            size_t grow = arow + r;
            bool ok = grow < (size_t)M;
            cp_async16z(base + so, &x[(ok ? grow : 0) * CH + k0 + 4 * c], ok ? 16u : 0u);
            cp_async16(base + 16384 + so, &g_wtf[(size_t)(bn + r) * CH + k0 + 4 * c]);
        }
    };

    auto compute = [&](int buf) {
        const uint32_t abase = sb + buf * 32768;
        const uint32_t bbase = abase + 16384;
        #pragma unroll
        for (int ks = 0; ks < 4; ks++) {
            const int kk = ks * 8 + t4;
            uint32_t a[2][4];
            #pragma unroll
            for (int mt = 0; mt < 2; mt++) {
                int r0 = warp_m + mt * 16 + g;
                a[mt][0] = f2tf32(lds32(taddr(abase, r0,     kk)));
                a[mt][1] = f2tf32(lds32(taddr(abase, r0 + 8, kk)));
                a[mt][2] = f2tf32(lds32(taddr(abase, r0,     kk + 4)));
                a[mt][3] = f2tf32(lds32(taddr(abase, r0 + 8, kk + 4)));
            }
            #pragma unroll
            for (int nt = 0; nt < 8; nt++) {
                int nr = warp_n + nt * 8 + g;
                uint32_t b[2];
                b[0] = f2tf32(lds32(taddr(bbase, nr, kk)));
                b[1] = f2tf32(lds32(taddr(bbase, nr, kk + 4)));
                mma_tf32(acc[0][nt], a[0], b);
                mma_tf32(acc[1][nt], a[1], b);
            }
        }
    };

    fill(0, 0);
    cp_commit();
    #pragma unroll 1
    for (int ch = 0; ch < 8; ch++) {
        if (ch < 7) {
            fill((ch + 1) & 1, ch + 1);
            cp_commit();
            cp_wait<1>();
        } else {
            cp_wait<0>();
        }
        __syncthreads();
        compute(ch & 1);
        __syncthreads();
    }

    #pragma unroll
    for (int mt = 0; mt < 2; mt++) {
        size_t r0 = arow + warp_m + mt * 16 + g;
        #pragma unroll
        for (int nt = 0; nt < 8; nt++) {
            int gc = bn + warp_n + nt * 8 + 2 * t4;
            if (r0 < (size_t)M)
                *(__half2*)&g_xwh[r0 * CH + gc] =
                    __floats2half2_rn(acc[mt][nt][0], acc[mt][nt][1]);
            if (r0 + 8 < (size_t)M)
                *(__half2*)&g_xwh[(r0 + 8) * CH + gc] =
                    __floats2half2_rn(acc[mt][nt][2], acc[mt][nt][3]);
        }
    }
}

// =============================================================== gather
// out[d][c0+c..] = b + sum val * xwh[src][..]  (fp16 reads, fp32 accum).
// 16 threads x 8ch per node, 16 nodes per block. Fully predicated BATCH-16:
// 16 outstanding LDG.128 per thread (under the ~55/warp cap) — doubles MLP
// vs batch-8; tail slots clamp to e-1 (L1 hits) with zeroed weight.
__global__ __launch_bounds__(256) void gather_half(const float* __restrict__ bias,
                                                   float* __restrict__ out, int c0) {
    int node = blockIdx.x * 16 + (threadIdx.x >> 4);
    if (node >= NN) return;
    int c = c0 + ((threadIdx.x & 15) << 3);
    int s = g_off[node], e = g_off[node + 1];

    float acc[8];
    #pragma unroll
    for (int j = 0; j < 8; j++) acc[j] = bias[c + j];

    auto fma8 = [&](float v, uint4 u) {
        const __half2* h = (const __half2*)&u;
        #pragma unroll
        for (int q = 0; q < 4; q++) {
            float2 f = __half22float2(h[q]);
            acc[2 * q]     += v * f.x;
            acc[2 * q + 1] += v * f.y;
        }
    };

    const __half* __restrict__ xw = g_xwh;
    for (int j = s; j < e; j += 16) {
        int2 m[16];
        #pragma unroll
        for (int q = 0; q < 16; q++) {
            int idx = j + q;
            if (idx >= e) idx = e - 1;
            m[q] = __ldg(&g_epack[idx]);
        }
        uint4 xv[16];
        #pragma unroll
        for (int q = 0; q < 16; q++)
            xv[q] = __ldg((const uint4*)&xw[(size_t)m[q].x * CH + c]);
        #pragma unroll
        for (int q = 0; q < 16; q++) {
            float v = (j + q < e) ? __int_as_float(m[q].y) : 0.f;
            fma8(v, xv[q]);
        }
    }

    float4 o0 = make_float4(acc[0], acc[1], acc[2], acc[3]);
    float4 o1 = make_float4(acc[4], acc[5], acc[6], acc[7]);
    *(float4*)&out[(size_t)node * CH + c]     = o0;
    *(float4*)&out[(size_t)node * CH + c + 4] = o1;
}

// =============================================================== launch
// DAG identical to R14 (measured best):
//   main:  wt_transpose -> gemm(n=0..127) -> gemm(n=128..255)
//   sB:    memset(deg) -> hist -> scan(smem) -> scatter
//   sC(hi):[gemm0 && scatter] -> gather cols 0..127
//   main:  [gemm1 && scatter] -> gather cols 128..255 -> join sC
extern "C" void kernel_launch(void* const* d_in, const int* in_sizes, int n_in,
                              void* d_out, int out_size) {
    const float* x    = (const float*)d_in[0];   // [N, 256]
    const float* W    = (const float*)d_in[1];   // [256, 256]
    const float* bias = (const float*)d_in[2];   // [256]
    const int*   esrc = (const int*)d_in[3];     // [E]
    const int*   edst = (const int*)d_in[4];     // [E]
    const float* eval = (const float*)d_in[5];   // [E]
    float* out = (float*)d_out;

    int M = in_sizes[0] / CH;   // 50000
    int E = in_sizes[3];        // 800000

    cudaFuncSetAttribute(gemm_mma, cudaFuncAttributeMaxDynamicSharedMemorySize,
                         GEMM_SMEM);
    cudaFuncSetAttribute(scan_smem_kernel,
                         cudaFuncAttributeMaxDynamicSharedMemorySize, SCAN_SMEM);

    int prLow = 0, prHigh = 0;
    cudaDeviceGetStreamPriorityRange(&prLow, &prHigh);

    cudaStream_t sB, sC;
    cudaStreamCreateWithFlags(&sB, cudaStreamNonBlocking);
    cudaStreamCreateWithPriority(&sC, cudaStreamNonBlocking, prHigh);
    cudaEvent_t evRoot, evS, evG0, evC;
    cudaEventCreateWithFlags(&evRoot, cudaEventDisableTiming);
    cudaEventCreateWithFlags(&evS,    cudaEventDisableTiming);
    cudaEventCreateWithFlags(&evG0,   cudaEventDisableTiming);
    cudaEventCreateWithFlags(&evC,    cudaEventDisableTiming);

    // fork sB off the (captured) default stream
    cudaEventRecord(evRoot, 0);
    cudaStreamWaitEvent(sB, evRoot, 0);

    // ---- branch B: CSR-by-dst build ----
    void* degp = nullptr;
    cudaGetSymbolAddress(&degp, g_deg);
    cudaMemsetAsync(degp, 0, NN * sizeof(int), sB);
    hist_kernel<<<(E + 255) / 256, 256, 0, sB>>>(edst, E);
    scan_smem_kernel<<<1, 1024, SCAN_SMEM, sB>>>(E);
    scatter_kernel<<<(E + 255) / 256, 256, 0, sB>>>(esrc, edst, eval, E);
    cudaEventRecord(evS, sB);

    // ---- main branch: W transpose + tf32 GEMM halves ----
    dim3 wtb(32, 8);
    dim3 wtg(CH / 32, CH / 32);
    wt_kernel<<<wtg, wtb>>>(W);
    int mblk = (M + 127) / 128;   // 391
    gemm_mma<<<mblk, 256, GEMM_SMEM>>>(x, M, 0);
    cudaEventRecord(evG0, 0);
    gemm_mma<<<mblk, 256, GEMM_SMEM>>>(x, M, 128);

    // ---- branch C (high priority): gather cols 0..127, overlaps gemm1 ----
    cudaStreamWaitEvent(sC, evG0, 0);
    cudaStreamWaitEvent(sC, evS, 0);
    gather_half<<<(NN + 15) / 16, 256, 0, sC>>>(bias, out, 0);
    cudaEventRecord(evC, sC);

    // ---- main branch: gather cols 128..255, then join everything ----
    cudaStreamWaitEvent(0, evS, 0);
    gather_half<<<(NN + 15) / 16, 256>>>(bias, out, 128);
    cudaStreamWaitEvent(0, evC, 0);

    cudaEventDestroy(evRoot);
    cudaEventDestroy(evS);
    cudaEventDestroy(evG0);
    cudaEventDestroy(evC);
    cudaStreamDestroy(sB);
    cudaStreamDestroy(sC);
}

// round 17
// speedup vs baseline: 1.5615x; 1.5615x over previous
#include <cuda_runtime.h>
#include <cuda_fp16.h>
#include <cstdint>

#define NN 50000
#define EE 800000
#define CH 256

// ---- scratch (device globals; no allocation allowed) ----
__device__ __align__(16) __half g_xwh[(size_t)NN * CH];    // x @ W (25.6 MB, fp16)
__device__ int   g_deg[NN];
__device__ int   g_off[NN + 1];
__device__ int   g_cur[NN];
__device__ __align__(16) int2  g_epack[EE];                // (src, val)
__device__ __align__(16) float g_wtf[CH * CH];             // W^T fp32 [n][k]

// =============================================================== helpers
__device__ __forceinline__ uint32_t smem_u32(const void* p) {
    uint32_t a;
    asm("{ .reg .u64 t; cvta.to.shared.u64 t, %1; cvt.u32.u64 %0, t; }"
        : "=r"(a) : "l"(p));
    return a;
}

__device__ __forceinline__ void cp_async16(uint32_t s, const void* g) {
    asm volatile("cp.async.cg.shared.global [%0], [%1], 16;" :: "r"(s), "l"(g));
}
__device__ __forceinline__ void cp_async16z(uint32_t s, const void* g, unsigned sz) {
    asm volatile("cp.async.cg.shared.global [%0], [%1], 16, %2;"
                 :: "r"(s), "l"(g), "r"(sz));
}
__device__ __forceinline__ void cp_commit() {
    asm volatile("cp.async.commit_group;" ::: "memory");
}
template <int N>
__device__ __forceinline__ void cp_wait() {
    asm volatile("cp.async.wait_group %0;" :: "n"(N) : "memory");
}

__device__ __forceinline__ uint32_t lds32(uint32_t addr) {
    uint32_t u;
    asm volatile("ld.shared.b32 %0, [%1];" : "=r"(u) : "r"(addr));
    return u;
}

__device__ __forceinline__ uint32_t f2tf32(uint32_t bits) {
    float v = __uint_as_float(bits);
    uint32_t t;
    asm("cvt.rna.tf32.f32 %0, %1;" : "=r"(t) : "f"(v));
    return t;
}

// D(fp32) += A(tf32) * B(tf32), m16n8k8
__device__ __forceinline__ void mma_tf32(float* c, const uint32_t* a, const uint32_t* b) {
    asm volatile(
        "mma.sync.aligned.m16n8k8.row.col.f32.tf32.tf32.f32 "
        "{%0,%1,%2,%3}, {%4,%5,%6,%7}, {%8,%9}, {%0,%1,%2,%3};"
        : "+f"(c[0]), "+f"(c[1]), "+f"(c[2]), "+f"(c[3])
        : "r"(a[0]), "r"(a[1]), "r"(a[2]), "r"(a[3]), "r"(b[0]), "r"(b[1]));
}

// =============================================================== CSR build
__global__ void hist_kernel(const int* __restrict__ dst, int E) {
    int i = blockIdx.x * blockDim.x + threadIdx.x;
    if (i < E) atomicAdd(&g_deg[dst[i]], 1);
}

// single-pass SMEM scan: 1024 threads x 49 elements each (50176 >= NN)
#define SCAN_PER_T 49
#define SCAN_PAD   (1024 * SCAN_PER_T)           // 50176
#define SCAN_SMEM  (SCAN_PAD * 4)                // 200704 B

__global__ __launch_bounds__(1024) void scan_smem_kernel(int E) {
    extern __shared__ int sd[];
    __shared__ int wsum[32];
    int tid = threadIdx.x, lane = tid & 31, warp = tid >> 5;

    for (int i = tid; i < SCAN_PAD; i += 1024)
        sd[i] = (i < NN) ? g_deg[i] : 0;
    __syncthreads();

    int base = tid * SCAN_PER_T;
    int local = 0;
    for (int j = 0; j < SCAN_PER_T; j++) local += sd[base + j];

    int x = local;
    #pragma unroll
    for (int o = 1; o < 32; o <<= 1) {
        int y = __shfl_up_sync(0xffffffffu, x, o);
        if (lane >= o) x += y;
    }
    if (lane == 31) wsum[warp] = x;
    __syncthreads();
    if (warp == 0) {
        int t = wsum[lane];
        #pragma unroll
        for (int o = 1; o < 32; o <<= 1) {
            int y = __shfl_up_sync(0xffffffffu, t, o);
            if (lane >= o) t += y;
        }
        wsum[lane] = t;
    }
    __syncthreads();
    int run = x - local + (warp > 0 ? wsum[warp - 1] : 0);

    for (int j = 0; j < SCAN_PER_T; j++) {
        int v = sd[base + j];
        sd[base + j] = run;
        run += v;
    }
    __syncthreads();
    for (int i = tid; i < NN; i += 1024) {
        int v = sd[i];
        g_off[i] = v;
        g_cur[i] = v;
    }
    if (tid == 0) g_off[NN] = E;
}

__global__ void scatter_kernel(const int* __restrict__ src,
                               const int* __restrict__ dst,
                               const float* __restrict__ val, int E) {
    int i = blockIdx.x * blockDim.x + threadIdx.x;
    if (i < E) {
        int p = atomicAdd(&g_cur[dst[i]], 1);
        g_epack[p] = make_int2(src[i], __float_as_int(val[i]));
    }
}

// =============================================================== W transpose
__global__ void wt_kernel(const float* __restrict__ W) {
    __shared__ float t[32][33];
    int bx = blockIdx.x * 32, by = blockIdx.y * 32;
    int tx = threadIdx.x, ty = threadIdx.y;
    #pragma unroll
    for (int r = 0; r < 32; r += 8)
        t[ty + r][tx] = W[(size_t)(bx + ty + r) * CH + by + tx];
    __syncthreads();
    #pragma unroll
    for (int r = 0; r < 32; r += 8)
        g_wtf[(size_t)(by + ty + r) * CH + bx + tx] = t[tx][ty + r];
}

// =============================================================== tf32 GEMM
// (R14 version, unchanged — measured good)
#define GEMM_SMEM 65536

__global__ __launch_bounds__(256, 2) void gemm_mma(const float* __restrict__ x,
                                                   int M, int bn) {
    extern __shared__ char smem[];
    const uint32_t sb = smem_u32(smem);
    const int tid  = threadIdx.x;
    const int lane = tid & 31;
    const int wid  = tid >> 5;
    const int warp_m = (wid & 3) * 32;
    const int warp_n = (wid >> 2) * 64;
    const size_t arow = (size_t)blockIdx.x * 128;
    const int g  = lane >> 2;
    const int t4 = lane & 3;

    float acc[2][8][4];
    #pragma unroll
    for (int mt = 0; mt < 2; mt++)
        #pragma unroll
        for (int nt = 0; nt < 8; nt++)
            #pragma unroll
            for (int j = 0; j < 4; j++) acc[mt][nt][j] = 0.f;

    auto taddr = [](uint32_t base, int r, int k) {
        return base + (uint32_t)(r * 128 + (((k >> 2) ^ (r & 7)) * 16) + (k & 3) * 4);
    };

    auto fill = [&](int buf, int ch) {
        const int k0 = ch * 32;
        const uint32_t base = sb + buf * 32768;
        #pragma unroll
        for (int i = 0; i < 4; i++) {
            int chunk = tid + i * 256;
            int r = chunk >> 3, c = chunk & 7;
            uint32_t so = (uint32_t)(r * 128 + ((c ^ (r & 7)) * 16));
            size_t grow = arow + r;
            bool ok = grow < (size_t)M;
            cp_async16z(base + so, &x[(ok ? grow : 0) * CH + k0 + 4 * c], ok ? 16u : 0u);
            cp_async16(base + 16384 + so, &g_wtf[(size_t)(bn + r) * CH + k0 + 4 * c]);
        }
    };

    auto compute = [&](int buf) {
        const uint32_t abase = sb + buf * 32768;
        const uint32_t bbase = abase + 16384;
        #pragma unroll
        for (int ks = 0; ks < 4; ks++) {
            const int kk = ks * 8 + t4;
            uint32_t a[2][4];
            #pragma unroll
            for (int mt = 0; mt < 2; mt++) {
                int r0 = warp_m + mt * 16 + g;
                a[mt][0] = f2tf32(lds32(taddr(abase, r0,     kk)));
                a[mt][1] = f2tf32(lds32(taddr(abase, r0 + 8, kk)));
                a[mt][2] = f2tf32(lds32(taddr(abase, r0,     kk + 4)));
                a[mt][3] = f2tf32(lds32(taddr(abase, r0 + 8, kk + 4)));
            }
            #pragma unroll
            for (int nt = 0; nt < 8; nt++) {
                int nr = warp_n + nt * 8 + g;
                uint32_t b[2];
                b[0] = f2tf32(lds32(taddr(bbase, nr, kk)));
                b[1] = f2tf32(lds32(taddr(bbase, nr, kk + 4)));
                mma_tf32(acc[0][nt], a[0], b);
                mma_tf32(acc[1][nt], a[1], b);
            }
        }
    };

    fill(0, 0);
    cp_commit();
    #pragma unroll 1
    for (int ch = 0; ch < 8; ch++) {
        if (ch < 7) {
            fill((ch + 1) & 1, ch + 1);
            cp_commit();
            cp_wait<1>();
        } else {
            cp_wait<0>();
        }
        __syncthreads();
        compute(ch & 1);
        __syncthreads();
    }

    #pragma unroll
    for (int mt = 0; mt < 2; mt++) {
        size_t r0 = arow + warp_m + mt * 16 + g;
        #pragma unroll
        for (int nt = 0; nt < 8; nt++) {
            int gc = bn + warp_n + nt * 8 + 2 * t4;
            if (r0 < (size_t)M)
                *(__half2*)&g_xwh[r0 * CH + gc] =
                    __floats2half2_rn(acc[mt][nt][0], acc[mt][nt][1]);
            if (r0 + 8 < (size_t)M)
                *(__half2*)&g_xwh[(r0 + 8) * CH + gc] =
                    __floats2half2_rn(acc[mt][nt][2], acc[mt][nt][3]);
        }
    }
}

// =============================================================== gather
// (R14/R12 measured-best version — batch-8, ~70 regs, no spill)
// out[d][c0+c..] = b + sum val * xwh[src][..]  (fp16 reads, fp32 accum).
// 16 threads x 8ch per node, 16 nodes per block; fully predicated batch-8.
__global__ __launch_bounds__(256) void gather_half(const float* __restrict__ bias,
                                                   float* __restrict__ out, int c0) {
    int node = blockIdx.x * 16 + (threadIdx.x >> 4);
    if (node >= NN) return;
    int c = c0 + ((threadIdx.x & 15) << 3);
    int s = g_off[node], e = g_off[node + 1];

    float acc[8];
    #pragma unroll
    for (int j = 0; j < 8; j++) acc[j] = bias[c + j];

    auto fma8 = [&](float v, uint4 u) {
        const __half2* h = (const __half2*)&u;
        #pragma unroll
        for (int q = 0; q < 4; q++) {
            float2 f = __half22float2(h[q]);
            acc[2 * q]     += v * f.x;
            acc[2 * q + 1] += v * f.y;
        }
    };

    const __half* __restrict__ xw = g_xwh;
    for (int j = s; j < e; j += 8) {
        int2 m[8];
        #pragma unroll
        for (int q = 0; q < 8; q++) {
            int idx = j + q;
            if (idx >= e) idx = e - 1;
            m[q] = __ldg(&g_epack[idx]);
        }
        uint4 xv[8];
        #pragma unroll
        for (int q = 0; q < 8; q++)
            xv[q] = __ldg((const uint4*)&xw[(size_t)m[q].x * CH + c]);
        #pragma unroll
        for (int q = 0; q < 8; q++) {
            float v = (j + q < e) ? __int_as_float(m[q].y) : 0.f;
            fma8(v, xv[q]);
        }
    }

    float4 o0 = make_float4(acc[0], acc[1], acc[2], acc[3]);
    float4 o1 = make_float4(acc[4], acc[5], acc[6], acc[7]);
    *(float4*)&out[(size_t)node * CH + c]     = o0;
    *(float4*)&out[(size_t)node * CH + c + 4] = o1;
}

// =============================================================== launch
// DAG identical to R14 (measured best):
//   main:  wt_transpose -> gemm(n=0..127) -> gemm(n=128..255)
//   sB:    memset(deg) -> hist -> scan(smem) -> scatter
//   sC(hi):[gemm0 && scatter] -> gather cols 0..127
//   main:  [gemm1 && scatter] -> gather cols 128..255 -> join sC
extern "C" void kernel_launch(void* const* d_in, const int* in_sizes, int n_in,
                              void* d_out, int out_size) {
    const float* x    = (const float*)d_in[0];   // [N, 256]
    const float* W    = (const float*)d_in[1];   // [256, 256]
    const float* bias = (const float*)d_in[2];   // [256]
    const int*   esrc = (const int*)d_in[3];     // [E]
    const int*   edst = (const int*)d_in[4];     // [E]
    const float* eval = (const float*)d_in[5];   // [E]
    float* out = (float*)d_out;

    int M = in_sizes[0] / CH;   // 50000
    int E = in_sizes[3];        // 800000

    cudaFuncSetAttribute(gemm_mma, cudaFuncAttributeMaxDynamicSharedMemorySize,
                         GEMM_SMEM);
    cudaFuncSetAttribute(scan_smem_kernel,
                         cudaFuncAttributeMaxDynamicSharedMemorySize, SCAN_SMEM);

    int prLow = 0, prHigh = 0;
    cudaDeviceGetStreamPriorityRange(&prLow, &prHigh);

    cudaStream_t sB, sC;
    cudaStreamCreateWithFlags(&sB, cudaStreamNonBlocking);
    cudaStreamCreateWithPriority(&sC, cudaStreamNonBlocking, prHigh);
    cudaEvent_t evRoot, evS, evG0, evC;
    cudaEventCreateWithFlags(&evRoot, cudaEventDisableTiming);
    cudaEventCreateWithFlags(&evS,    cudaEventDisableTiming);
    cudaEventCreateWithFlags(&evG0,   cudaEventDisableTiming);
    cudaEventCreateWithFlags(&evC,    cudaEventDisableTiming);

    // fork sB off the (captured) default stream
    cudaEventRecord(evRoot, 0);
    cudaStreamWaitEvent(sB, evRoot, 0);

    // ---- branch B: CSR-by-dst build ----
    void* degp = nullptr;
    cudaGetSymbolAddress(&degp, g_deg);
    cudaMemsetAsync(degp, 0, NN * sizeof(int), sB);
    hist_kernel<<<(E + 255) / 256, 256, 0, sB>>>(edst, E);
    scan_smem_kernel<<<1, 1024, SCAN_SMEM, sB>>>(E);
    scatter_kernel<<<(E + 255) / 256, 256, 0, sB>>>(esrc, edst, eval, E);
    cudaEventRecord(evS, sB);

    // ---- main branch: W transpose + tf32 GEMM halves ----
    dim3 wtb(32, 8);
    dim3 wtg(CH / 32, CH / 32);
    wt_kernel<<<wtg, wtb>>>(W);
    int mblk = (M + 127) / 128;   // 391
    gemm_mma<<<mblk, 256, GEMM_SMEM>>>(x, M, 0);
    cudaEventRecord(evG0, 0);
    gemm_mma<<<mblk, 256, GEMM_SMEM>>>(x, M, 128);

    // ---- branch C (high priority): gather cols 0..127, overlaps gemm1 ----
    cudaStreamWaitEvent(sC, evG0, 0);
    cudaStreamWaitEvent(sC, evS, 0);
    gather_half<<<(NN + 15) / 16, 256, 0, sC>>>(bias, out, 0);
    cudaEventRecord(evC, sC);

    // ---- main branch: gather cols 128..255, then join everything ----
    cudaStreamWaitEvent(0, evS, 0);
    gather_half<<<(NN + 15) / 16, 256>>>(bias, out, 128);
    cudaStreamWaitEvent(0, evC, 0);

    cudaEventDestroy(evRoot);
    cudaEventDestroy(evS);
    cudaEventDestroy(evG0);
    cudaEventDestroy(evC);
    cudaStreamDestroy(sB);
    cudaStreamDestroy(sC);
}